// round 6
// baseline (speedup 1.0000x reference)
#include <cuda_runtime.h>
#include <cuda_bf16.h>
#include <cstdint>
#include <cstddef>

// Problem constants (fixed by the dataset)
#define NP_ 100000
#define NQ_ 50000
#define D_  128
#define E_DEFAULT 600000

// ---------------------------------------------------------------------------
// Device scratch (static: no runtime allocation allowed)
// ---------------------------------------------------------------------------
__device__ float g_accP[(size_t)NP_ * D_];   // product->person aggregation accumulator
__device__ float g_accQ[(size_t)NQ_ * D_];   // person->product aggregation accumulator
__device__ float g_cntP[NP_];
__device__ float g_cntQ[NQ_];
__device__ float g_hP[(size_t)NP_ * D_];     // layer-0 person output (post ReLU)
__device__ float g_hQ[(size_t)NQ_ * D_];     // layer-0 product output (post ReLU)

// ---------------------------------------------------------------------------
// Packed f32x2 FMA (Blackwell) helpers
// ---------------------------------------------------------------------------
__device__ __forceinline__ void fma2(unsigned long long& acc,
                                     unsigned long long a,
                                     unsigned long long b) {
    asm("fma.rn.f32x2 %0, %1, %2, %0;" : "+l"(acc) : "l"(a), "l"(b));
}
__device__ __forceinline__ float2 unpack2(unsigned long long v) {
    float2 r;
    asm("mov.b64 {%0, %1}, %2;" : "=f"(r.x), "=f"(r.y) : "l"(v));
    return r;
}

// ---------------------------------------------------------------------------
// Zero accumulators + counts
// ---------------------------------------------------------------------------
__global__ void zero_kernel() {
    size_t i = (size_t)blockIdx.x * blockDim.x + threadIdx.x;
    size_t stride = (size_t)gridDim.x * blockDim.x;
    float4 z = make_float4(0.f, 0.f, 0.f, 0.f);
    float4* aP = reinterpret_cast<float4*>(g_accP);
    float4* aQ = reinterpret_cast<float4*>(g_accQ);
    const size_t nP4 = (size_t)NP_ * (D_ / 4);
    const size_t nQ4 = (size_t)NQ_ * (D_ / 4);
    for (size_t k = i; k < nP4; k += stride) aP[k] = z;
    for (size_t k = i; k < nQ4; k += stride) aQ[k] = z;
    for (size_t k = i; k < NP_; k += stride) g_cntP[k] = 0.f;
    for (size_t k = i; k < NQ_; k += stride) g_cntQ[k] = 0.f;
}

// ---------------------------------------------------------------------------
// Scatter-add: one warp per edge. Vector RED into L2.
// ---------------------------------------------------------------------------
template <bool TO_Q, bool SRC_H>
__global__ __launch_bounds__(256) void scatter_kernel(
    const float* __restrict__ xin,
    const int* __restrict__ src,
    const int* __restrict__ dst,
    int nE)
{
    const float* x = SRC_H ? (TO_Q ? g_hP : g_hQ) : xin;
    float* acc = TO_Q ? g_accQ : g_accP;
    float* cnt = TO_Q ? g_cntQ : g_cntP;

    int warp = (int)((blockIdx.x * blockDim.x + threadIdx.x) >> 5);
    int lane = threadIdx.x & 31;
    if (warp >= nE) return;

    int s = __ldg(src + warp);
    int d = __ldg(dst + warp);

    float4 v = *reinterpret_cast<const float4*>(x + (size_t)s * D_ + lane * 4);
    float* p = acc + (size_t)d * D_ + lane * 4;
    asm volatile("red.global.add.v4.f32 [%0], {%1, %2, %3, %4};"
                 :: "l"(p), "f"(v.x), "f"(v.y), "f"(v.z), "f"(v.w)
                 : "memory");
    if (lane == 0) atomicAdd(cnt + d, 1.0f);
}

// ---------------------------------------------------------------------------
// Fused SAGE linear:  out = (acc/max(cnt,1)) @ Wl + self @ Wr + b  [+ReLU]
//
// 128x128 tile, 256 threads, 8x8 microtile on packed f32x2 accumulators.
// K is a single 16-tile loop (8 tiles over scaled-acc@Wl, 8 over self@Wr).
// Pipelining: next tile's LDG issued before current tile's compute (register
// prefetch). A tile is stored to smem PRE-DUPLICATED as float2{v,v}, so the
// inner loop reads a-dups and b-pairs as raw 64-bit values — zero MOVs/kk.
// ---------------------------------------------------------------------------
#define BM 128
#define BK 16
#define AS_STRIDE 130   // float2 elements per As_dup row (2-elem pad)
#define BS_STRIDE 132   // floats per Bs row (4-float pad)

template <bool Q_SIDE, bool LAYER1>
__global__ __launch_bounds__(256, 2) void gemm_kernel(
    const float* __restrict__ xparam,
    const float* __restrict__ Wl,
    const float* __restrict__ Wr,
    const float* __restrict__ bias,
    float* __restrict__ outparam,
    int nrows)
{
    const float* accsrc = Q_SIDE ? g_accQ : g_accP;
    const float* cnt    = Q_SIDE ? g_cntQ : g_cntP;
    const float* self   = LAYER1 ? (Q_SIDE ? g_hQ : g_hP) : xparam;
    float*       out    = LAYER1 ? outparam : (Q_SIDE ? g_hQ : g_hP);

    __shared__ __align__(16) float2 As_dup[BK][AS_STRIDE]; // [k][m] duplicated
    __shared__ __align__(16) float  Bs[BK][BS_STRIDE];     // [k][n]
    __shared__ float rscale[BM];

    const int tid = threadIdx.x;
    const int tx = tid & 15;     // column group: cols tx*8 .. tx*8+7
    const int ty = tid >> 4;     // row group:    rows ty*8 .. ty*8+7
    const int row0 = blockIdx.x * BM;

    // A-load mapping: each thread owns one row-slice of the 128x16 tile
    const int ar = tid >> 1;             // local row 0..127
    const int ah = (tid & 1) * 8;        // k sub-offset 0 or 8
    const int agrow = row0 + ar;
    // B-load mapping
    const int bkr = tid >> 4;            // k row 0..15
    const int bc  = (tid & 15) * 8;      // column 0..120

    if (tid < BM) {
        int r = row0 + tid;
        float c = (r < nrows) ? cnt[r] : 1.f;
        rscale[tid] = 1.f / fmaxf(c, 1.f);
    }
    __syncthreads();
    const float myscale = rscale[ar];

    unsigned long long accr[8][4];
#pragma unroll
    for (int i = 0; i < 8; i++)
#pragma unroll
        for (int j = 0; j < 4; j++) accr[i][j] = 0ull;

    float4 va0, va1, vb0, vb1;

    // prefetch tile 0 (pass 0: A = acc, W = Wl, k0 = 0)
    {
        va0 = make_float4(0.f, 0.f, 0.f, 0.f); va1 = va0;
        if (agrow < nrows) {
            const float* ap = accsrc + (size_t)agrow * D_ + ah;
            va0 = *reinterpret_cast<const float4*>(ap);
            va1 = *reinterpret_cast<const float4*>(ap + 4);
        }
        const float* wp = Wl + (size_t)bkr * D_ + bc;
        vb0 = *reinterpret_cast<const float4*>(wp);
        vb1 = *reinterpret_cast<const float4*>(wp + 4);
    }

#pragma unroll 1
    for (int t = 0; t < 16; ++t) {
        const bool pass0 = (t < 8);
        // ---- store prefetched tile to smem (A duplicated + scaled) ----
        {
            float sc = pass0 ? myscale : 1.f;
            float v[8] = {va0.x, va0.y, va0.z, va0.w, va1.x, va1.y, va1.z, va1.w};
#pragma unroll
            for (int j = 0; j < 8; j++) {
                float s = v[j] * sc;
                As_dup[ah + j][ar] = make_float2(s, s);
            }
            *reinterpret_cast<float4*>(&Bs[bkr][bc])     = vb0;
            *reinterpret_cast<float4*>(&Bs[bkr][bc + 4]) = vb1;
        }
        __syncthreads();

        // ---- prefetch next tile while computing this one ----
        if (t < 15) {
            int tn = t + 1;
            int k0 = (tn & 7) * BK;
            const float* A = (tn < 8) ? accsrc : self;
            const float* W = (tn < 8) ? Wl : Wr;
            va0 = make_float4(0.f, 0.f, 0.f, 0.f); va1 = va0;
            if (agrow < nrows) {
                const float* ap = A + (size_t)agrow * D_ + k0 + ah;
                va0 = *reinterpret_cast<const float4*>(ap);
                va1 = *reinterpret_cast<const float4*>(ap + 4);
            }
            const float* wp = W + (size_t)(k0 + bkr) * D_ + bc;
            vb0 = *reinterpret_cast<const float4*>(wp);
            vb1 = *reinterpret_cast<const float4*>(wp + 4);
        }

        // ---- compute: 16 k-steps, 8x8 microtile, zero MOVs ----
#pragma unroll
        for (int kk = 0; kk < BK; ++kk) {
            ulonglong2 a01 = *reinterpret_cast<const ulonglong2*>(&As_dup[kk][ty * 8 + 0]);
            ulonglong2 a23 = *reinterpret_cast<const ulonglong2*>(&As_dup[kk][ty * 8 + 2]);
            ulonglong2 a45 = *reinterpret_cast<const ulonglong2*>(&As_dup[kk][ty * 8 + 4]);
            ulonglong2 a67 = *reinterpret_cast<const ulonglong2*>(&As_dup[kk][ty * 8 + 6]);
            ulonglong2 b01 = *reinterpret_cast<const ulonglong2*>(&Bs[kk][tx * 8]);
            ulonglong2 b23 = *reinterpret_cast<const ulonglong2*>(&Bs[kk][tx * 8 + 4]);
            unsigned long long av[8] = {a01.x, a01.y, a23.x, a23.y,
                                        a45.x, a45.y, a67.x, a67.y};
            unsigned long long bv[4] = {b01.x, b01.y, b23.x, b23.y};
#pragma unroll
            for (int i = 0; i < 8; i++) {
#pragma unroll
                for (int j = 0; j < 4; j++) fma2(accr[i][j], av[i], bv[j]);
            }
        }
        __syncthreads();
    }

    // ---- epilogue: bias, optional ReLU, store ----
    float bcol[8];
#pragma unroll
    for (int j = 0; j < 8; j++) bcol[j] = bias[tx * 8 + j];

#pragma unroll
    for (int i = 0; i < 8; i++) {
        int r = row0 + ty * 8 + i;
        if (r >= nrows) continue;
        float o[8];
#pragma unroll
        for (int j = 0; j < 4; j++) {
            float2 v = unpack2(accr[i][j]);
            o[2 * j] = v.x;
            o[2 * j + 1] = v.y;
        }
#pragma unroll
        for (int j = 0; j < 8; j++) {
            o[j] += bcol[j];
            if (!LAYER1) o[j] = fmaxf(o[j], 0.f);  // ReLU after layer 0 only
        }
        float4* op = reinterpret_cast<float4*>(out + (size_t)r * D_ + tx * 8);
        op[0] = make_float4(o[0], o[1], o[2], o[3]);
        op[1] = make_float4(o[4], o[5], o[6], o[7]);
    }
}

// ---------------------------------------------------------------------------
// kernel_launch — inputs classified by element count (see R4 notes)
// Output: [h_p (NP*D) | h_q (NQ*D)]
// ---------------------------------------------------------------------------
extern "C" void kernel_launch(void* const* d_in, const int* in_sizes, int n_in,
                              void* d_out, int out_size)
{
    (void)out_size;
    const float* x_p = nullptr;
    const float* x_q = nullptr;
    const float* W[8] = {nullptr};
    const float* b[4] = {nullptr};
    const int*   eidx[4] = {nullptr};
    int wi = 0, bi = 0, ei = 0;
    int E = E_DEFAULT;

    for (int i = 0; i < n_in; i++) {
        int n = in_sizes[i];
        if (n == NP_ * D_)            x_p = (const float*)d_in[i];
        else if (n == NQ_ * D_)       x_q = (const float*)d_in[i];
        else if (n == D_ * D_)        { if (wi < 8) W[wi++] = (const float*)d_in[i]; }
        else if (n == D_)             { if (bi < 4) b[bi++] = (const float*)d_in[i]; }
        else                          { if (ei < 4) { eidx[ei++] = (const int*)d_in[i]; E = n; } }
    }

    const int* src_pv = eidx[0];
    const int* dst_pv = eidx[1];
    const int* src_vp = eidx[2];
    const int* dst_vp = eidx[3];
    float* out = (float*)d_out;

    int sblocks = (E * 32 + 255) / 256;           // one warp per edge
    dim3 gQ((NQ_ + BM - 1) / BM);
    dim3 gP((NP_ + BM - 1) / BM);

    // ---- Layer 0 ----
    zero_kernel<<<4096, 256>>>();
    scatter_kernel<true,  false><<<sblocks, 256>>>(x_p, src_pv, dst_pv, E);  // person -> product
    scatter_kernel<false, false><<<sblocks, 256>>>(x_q, src_vp, dst_vp, E);  // product -> person
    gemm_kernel<true,  false><<<gQ, 256>>>(x_q, W[0], W[1], b[0], nullptr, NQ_); // -> g_hQ (ReLU)
    gemm_kernel<false, false><<<gP, 256>>>(x_p, W[2], W[3], b[1], nullptr, NP_); // -> g_hP (ReLU)

    // ---- Layer 1 ----
    zero_kernel<<<4096, 256>>>();
    scatter_kernel<true,  true><<<sblocks, 256>>>(nullptr, src_pv, dst_pv, E); // g_hP -> product
    scatter_kernel<false, true><<<sblocks, 256>>>(nullptr, src_vp, dst_vp, E); // g_hQ -> person
    gemm_kernel<true,  true><<<gQ, 256>>>(nullptr, W[4], W[5], b[2],
                                          out + (size_t)NP_ * D_, NQ_);        // h_q
    gemm_kernel<false, true><<<gP, 256>>>(nullptr, W[6], W[7], b[3],
                                          out, NP_);                           // h_p
}

// round 7
// speedup vs baseline: 1.2954x; 1.2954x over previous
#include <cuda_runtime.h>
#include <cuda_bf16.h>
#include <cstdint>
#include <cstddef>

// Problem constants (fixed by the dataset)
#define NP_ 100000
#define NQ_ 50000
#define D_  128
#define E_DEFAULT 600000

// ---------------------------------------------------------------------------
// Device scratch (static: no runtime allocation allowed)
// ---------------------------------------------------------------------------
__device__ float g_accP[(size_t)NP_ * D_];   // product->person aggregation accumulator
__device__ float g_accQ[(size_t)NQ_ * D_];   // person->product aggregation accumulator
__device__ float g_cntP[NP_];
__device__ float g_cntQ[NQ_];
__device__ float g_hP[(size_t)NP_ * D_];     // layer-0 person output (post ReLU)
__device__ float g_hQ[(size_t)NQ_ * D_];     // layer-0 product output (post ReLU)

// ---------------------------------------------------------------------------
// Packed f32x2 FMA (Blackwell) helpers
// ---------------------------------------------------------------------------
__device__ __forceinline__ unsigned long long pack2dup(float a) {
    unsigned long long r;
    asm("mov.b64 %0, {%1, %1};" : "=l"(r) : "f"(a));
    return r;
}
__device__ __forceinline__ void fma2(unsigned long long& acc,
                                     unsigned long long a,
                                     unsigned long long b) {
    asm("fma.rn.f32x2 %0, %1, %2, %0;" : "+l"(acc) : "l"(a), "l"(b));
}
__device__ __forceinline__ float2 unpack2(unsigned long long v) {
    float2 r;
    asm("mov.b64 {%0, %1}, %2;" : "=f"(r.x), "=f"(r.y) : "l"(v));
    return r;
}

// ---------------------------------------------------------------------------
// Zero accumulators + counts
// ---------------------------------------------------------------------------
__global__ void zero_kernel() {
    size_t i = (size_t)blockIdx.x * blockDim.x + threadIdx.x;
    size_t stride = (size_t)gridDim.x * blockDim.x;
    float4 z = make_float4(0.f, 0.f, 0.f, 0.f);
    float4* aP = reinterpret_cast<float4*>(g_accP);
    float4* aQ = reinterpret_cast<float4*>(g_accQ);
    const size_t nP4 = (size_t)NP_ * (D_ / 4);
    const size_t nQ4 = (size_t)NQ_ * (D_ / 4);
    for (size_t k = i; k < nP4; k += stride) aP[k] = z;
    for (size_t k = i; k < nQ4; k += stride) aQ[k] = z;
    for (size_t k = i; k < NP_; k += stride) g_cntP[k] = 0.f;
    for (size_t k = i; k < NQ_; k += stride) g_cntQ[k] = 0.f;
}

// ---------------------------------------------------------------------------
// Merged scatter-add for one layer: warps [0,E) do person->product (pv),
// warps [E,2E) do product->person (vp). One warp per edge, vector RED.
//   SRC_H: gather from layer-0 hidden state instead of the kernel-arg x.
// ---------------------------------------------------------------------------
template <bool SRC_H>
__global__ __launch_bounds__(256) void scatter_kernel(
    const float* __restrict__ x_p_in,
    const float* __restrict__ x_q_in,
    const int* __restrict__ src_pv,
    const int* __restrict__ dst_pv,
    const int* __restrict__ src_vp,
    const int* __restrict__ dst_vp,
    int nE)
{
    int warp = (int)((blockIdx.x * blockDim.x + threadIdx.x) >> 5);
    int lane = threadIdx.x & 31;
    if (warp >= 2 * nE) return;

    const float* x;
    float* acc;
    float* cnt;
    const int* src;
    const int* dst;
    int e;
    if (warp < nE) {              // person -> product
        e = warp;
        x = SRC_H ? g_hP : x_p_in;
        acc = g_accQ; cnt = g_cntQ; src = src_pv; dst = dst_pv;
    } else {                      // product -> person
        e = warp - nE;
        x = SRC_H ? g_hQ : x_q_in;
        acc = g_accP; cnt = g_cntP; src = src_vp; dst = dst_vp;
    }

    int s = __ldg(src + e);
    int d = __ldg(dst + e);

    float4 v = *reinterpret_cast<const float4*>(x + (size_t)s * D_ + lane * 4);
    float* p = acc + (size_t)d * D_ + lane * 4;
    asm volatile("red.global.add.v4.f32 [%0], {%1, %2, %3, %4};"
                 :: "l"(p), "f"(v.x), "f"(v.y), "f"(v.z), "f"(v.w)
                 : "memory");
    if (lane == 0) atomicAdd(cnt + d, 1.0f);
}

// ---------------------------------------------------------------------------
// Merged fused SAGE linear for one layer (both node types in one launch):
//   out = (acc/max(cnt,1)) @ Wl + self @ Wr + b   [+ReLU if !LAYER1]
//
// Blocks [0, nQb) handle product rows, [nQb, nQb+nPb) person rows.
// 128x128 tile, 256 threads, 8x8 microtile on packed f32x2 accumulators.
// Thread's 8 output cols are {tx*4..tx*4+3} u {64+tx*4..67+tx*4} so each B
// LDS.128 is conflict-free (16 threads x consecutive 16B).
// Pipelining: double-buffered smem + register prefetch of the next BK tile;
// one __syncthreads per tile.
// ---------------------------------------------------------------------------
#define BM 128
#define BK 16
#define AS_STRIDE 132
#define BS_STRIDE 132

template <bool LAYER1>
__global__ __launch_bounds__(256, 2) void gemm_kernel(
    const float* __restrict__ x_q_in, const float* __restrict__ x_p_in,
    const float* __restrict__ Wl_q, const float* __restrict__ Wr_q,
    const float* __restrict__ b_q,
    const float* __restrict__ Wl_p, const float* __restrict__ Wr_p,
    const float* __restrict__ b_p,
    float* __restrict__ out_q, float* __restrict__ out_p,
    int nQb)
{
    const bool qside = ((int)blockIdx.x) < nQb;
    const int blk = qside ? (int)blockIdx.x : (int)blockIdx.x - nQb;
    const int nrows = qside ? NQ_ : NP_;
    const float* accsrc = qside ? g_accQ : g_accP;
    const float* cnt    = qside ? g_cntQ : g_cntP;
    const float* self   = LAYER1 ? (qside ? g_hQ : g_hP) : (qside ? x_q_in : x_p_in);
    const float* Wl     = qside ? Wl_q : Wl_p;
    const float* Wr     = qside ? Wr_q : Wr_p;
    const float* bias   = qside ? b_q  : b_p;
    float*       out    = LAYER1 ? (qside ? out_q : out_p) : (qside ? g_hQ : g_hP);

    __shared__ __align__(16) float As[2][BK][AS_STRIDE];  // [k][m]
    __shared__ __align__(16) float Bs[2][BK][BS_STRIDE];  // [k][n]
    __shared__ float rscale[BM];

    const int tid = threadIdx.x;
    const int tx = tid & 15;     // column group
    const int ty = tid >> 4;     // row group: rows ty*8 .. ty*8+7
    const int row0 = blk * BM;

    // A-load mapping: thread owns 8 contiguous k of one row
    const int ar = tid >> 1;             // local row 0..127
    const int ah = (tid & 1) * 8;        // k sub-offset 0 or 8
    const int agrow = row0 + ar;
    // B-load mapping
    const int bkr = tid >> 4;            // k row 0..15
    const int bc  = (tid & 15) * 8;      // column 0..120

    if (tid < BM) {
        int r = row0 + tid;
        float c = (r < nrows) ? cnt[r] : 1.f;
        rscale[tid] = 1.f / fmaxf(c, 1.f);
    }
    __syncthreads();
    const float myscale = rscale[ar];

    unsigned long long accr[8][4];
#pragma unroll
    for (int i = 0; i < 8; i++)
#pragma unroll
        for (int j = 0; j < 4; j++) accr[i][j] = 0ull;

    float4 va0, va1, vb0, vb1;

    // ---- prefetch tile 0 (pass 0: A = acc, W = Wl, k0 = 0) ----
    va0 = make_float4(0.f, 0.f, 0.f, 0.f); va1 = va0;
    if (agrow < nrows) {
        const float* ap = accsrc + (size_t)agrow * D_ + ah;
        va0 = *reinterpret_cast<const float4*>(ap);
        va1 = *reinterpret_cast<const float4*>(ap + 4);
    }
    {
        const float* wp = Wl + (size_t)bkr * D_ + bc;
        vb0 = *reinterpret_cast<const float4*>(wp);
        vb1 = *reinterpret_cast<const float4*>(wp + 4);
    }
    // ---- store tile 0 (scaled) ----
    {
        float v[8] = {va0.x, va0.y, va0.z, va0.w, va1.x, va1.y, va1.z, va1.w};
#pragma unroll
        for (int j = 0; j < 8; j++) As[0][ah + j][ar] = v[j] * myscale;
        *reinterpret_cast<float4*>(&Bs[0][bkr][bc])     = vb0;
        *reinterpret_cast<float4*>(&Bs[0][bkr][bc + 4]) = vb1;
    }
    __syncthreads();

#pragma unroll 2
    for (int t = 0; t < 16; ++t) {
        const int buf = t & 1;

        // ---- prefetch next tile into registers ----
        if (t < 15) {
            int tn = t + 1;
            int k0 = (tn & 7) * BK;
            const float* A = (tn < 8) ? accsrc : self;
            const float* W = (tn < 8) ? Wl : Wr;
            va0 = make_float4(0.f, 0.f, 0.f, 0.f); va1 = va0;
            if (agrow < nrows) {
                const float* ap = A + (size_t)agrow * D_ + k0 + ah;
                va0 = *reinterpret_cast<const float4*>(ap);
                va1 = *reinterpret_cast<const float4*>(ap + 4);
            }
            const float* wp = W + (size_t)(k0 + bkr) * D_ + bc;
            vb0 = *reinterpret_cast<const float4*>(wp);
            vb1 = *reinterpret_cast<const float4*>(wp + 4);
        }

        // ---- compute current tile: 16 k-steps, 8x8 microtile ----
#pragma unroll
        for (int kk = 0; kk < BK; ++kk) {
            float4 a0 = *reinterpret_cast<const float4*>(&As[buf][kk][ty * 8]);
            float4 a1 = *reinterpret_cast<const float4*>(&As[buf][kk][ty * 8 + 4]);
            // conflict-free B reads: 16 threads x consecutive 16B
            ulonglong2 blo = *reinterpret_cast<const ulonglong2*>(&Bs[buf][kk][tx * 4]);
            ulonglong2 bhi = *reinterpret_cast<const ulonglong2*>(&Bs[buf][kk][64 + tx * 4]);
            unsigned long long bv[4] = {blo.x, blo.y, bhi.x, bhi.y};
            float av[8] = {a0.x, a0.y, a0.z, a0.w, a1.x, a1.y, a1.z, a1.w};
#pragma unroll
            for (int i = 0; i < 8; i++) {
                unsigned long long ap = pack2dup(av[i]);
                fma2(accr[i][0], ap, bv[0]);
                fma2(accr[i][1], ap, bv[1]);
                fma2(accr[i][2], ap, bv[2]);
                fma2(accr[i][3], ap, bv[3]);
            }
        }

        // ---- store prefetched tile into other buffer ----
        if (t < 15) {
            float sc = (t + 1 < 8) ? myscale : 1.f;
            float v[8] = {va0.x, va0.y, va0.z, va0.w, va1.x, va1.y, va1.z, va1.w};
#pragma unroll
            for (int j = 0; j < 8; j++) As[buf ^ 1][ah + j][ar] = v[j] * sc;
            *reinterpret_cast<float4*>(&Bs[buf ^ 1][bkr][bc])     = vb0;
            *reinterpret_cast<float4*>(&Bs[buf ^ 1][bkr][bc + 4]) = vb1;
        }
        __syncthreads();
    }

    // ---- epilogue: bias, optional ReLU, store (cols tx*4 and 64+tx*4) ----
    float bcol[8];
#pragma unroll
    for (int j = 0; j < 4; j++) {
        bcol[j]     = bias[tx * 4 + j];
        bcol[4 + j] = bias[64 + tx * 4 + j];
    }

#pragma unroll
    for (int i = 0; i < 8; i++) {
        int r = row0 + ty * 8 + i;
        if (r >= nrows) continue;
        float o[8];
#pragma unroll
        for (int j = 0; j < 4; j++) {
            float2 v = unpack2(accr[i][j]);
            o[2 * j]     = v.x;
            o[2 * j + 1] = v.y;
        }
#pragma unroll
        for (int j = 0; j < 8; j++) {
            o[j] += bcol[j];
            if (!LAYER1) o[j] = fmaxf(o[j], 0.f);  // ReLU after layer 0 only
        }
        float* orow = out + (size_t)r * D_;
        *reinterpret_cast<float4*>(orow + tx * 4)      = make_float4(o[0], o[1], o[2], o[3]);
        *reinterpret_cast<float4*>(orow + 64 + tx * 4) = make_float4(o[4], o[5], o[6], o[7]);
    }
}

// ---------------------------------------------------------------------------
// kernel_launch — inputs classified by element count (see R4 notes)
// Output: [h_p (NP*D) | h_q (NQ*D)]
// ---------------------------------------------------------------------------
extern "C" void kernel_launch(void* const* d_in, const int* in_sizes, int n_in,
                              void* d_out, int out_size)
{
    (void)out_size;
    const float* x_p = nullptr;
    const float* x_q = nullptr;
    const float* W[8] = {nullptr};
    const float* b[4] = {nullptr};
    const int*   eidx[4] = {nullptr};
    int wi = 0, bi = 0, ei = 0;
    int E = E_DEFAULT;

    for (int i = 0; i < n_in; i++) {
        int n = in_sizes[i];
        if (n == NP_ * D_)            x_p = (const float*)d_in[i];
        else if (n == NQ_ * D_)       x_q = (const float*)d_in[i];
        else if (n == D_ * D_)        { if (wi < 8) W[wi++] = (const float*)d_in[i]; }
        else if (n == D_)             { if (bi < 4) b[bi++] = (const float*)d_in[i]; }
        else                          { if (ei < 4) { eidx[ei++] = (const int*)d_in[i]; E = n; } }
    }

    const int* src_pv = eidx[0];
    const int* dst_pv = eidx[1];
    const int* src_vp = eidx[2];
    const int* dst_vp = eidx[3];
    float* out = (float*)d_out;
    float* out_p = out;
    float* out_q = out + (size_t)NP_ * D_;

    int sblocks = (2 * E * 32 + 255) / 256;       // one warp per edge, both types
    int nQb = (NQ_ + BM - 1) / BM;                // 391
    int nPb = (NP_ + BM - 1) / BM;                // 782
    dim3 gG(nQb + nPb);

    // ---- Layer 0 ----
    zero_kernel<<<4096, 256>>>();
    scatter_kernel<false><<<sblocks, 256>>>(x_p, x_q, src_pv, dst_pv, src_vp, dst_vp, E);
    gemm_kernel<false><<<gG, 256>>>(x_q, x_p,
                                    W[0], W[1], b[0],     // product side (pv)
                                    W[2], W[3], b[1],     // person side (vp)
                                    nullptr, nullptr, nQb);

    // ---- Layer 1 ----
    zero_kernel<<<4096, 256>>>();
    scatter_kernel<true><<<sblocks, 256>>>(x_p, x_q, src_pv, dst_pv, src_vp, dst_vp, E);
    gemm_kernel<true><<<gG, 256>>>(x_q, x_p,
                                   W[4], W[5], b[2],
                                   W[6], W[7], b[3],
                                   out_q, out_p, nQb);
}

// round 8
// speedup vs baseline: 1.3659x; 1.0545x over previous
#include <cuda_runtime.h>
#include <cuda_bf16.h>
#include <cstdint>
#include <cstddef>

// Problem constants (fixed by the dataset)
#define NP_ 100000
#define NQ_ 50000
#define D_  128
#define E_  600000

// ---------------------------------------------------------------------------
// Device scratch (static: no runtime allocation allowed)
// ---------------------------------------------------------------------------
__device__ float g_accP[(size_t)NP_ * D_];   // mean(product msgs) per person
__device__ float g_accQ[(size_t)NQ_ * D_];   // mean(person msgs) per product
__device__ float g_hP[(size_t)NP_ * D_];     // layer-0 person output (post ReLU)
__device__ float g_hQ[(size_t)NQ_ * D_];     // layer-0 product output (post ReLU)

// CSR (built once per launch; topology shared by both layers)
__device__ int g_degQ[NQ_];
__device__ int g_degP[NP_];
__device__ int g_offQ[NQ_ + 1];
__device__ int g_offP[NP_ + 1];
__device__ int g_curQ[NQ_];
__device__ int g_curP[NP_];
__device__ int g_csrQ[E_];    // person ids, grouped by product dst
__device__ int g_csrP[E_];    // product ids, grouped by person dst

// ---------------------------------------------------------------------------
// Packed f32x2 FMA (Blackwell) helpers
// ---------------------------------------------------------------------------
__device__ __forceinline__ unsigned long long pack2dup(float a) {
    unsigned long long r;
    asm("mov.b64 %0, {%1, %1};" : "=l"(r) : "f"(a));
    return r;
}
__device__ __forceinline__ void fma2(unsigned long long& acc,
                                     unsigned long long a,
                                     unsigned long long b) {
    asm("fma.rn.f32x2 %0, %1, %2, %0;" : "+l"(acc) : "l"(a), "l"(b));
}
__device__ __forceinline__ float2 unpack2(unsigned long long v) {
    float2 r;
    asm("mov.b64 {%0, %1}, %2;" : "=f"(r.x), "=f"(r.y) : "l"(v));
    return r;
}

// ---------------------------------------------------------------------------
// CSR build step 1: zero degree arrays
// ---------------------------------------------------------------------------
__global__ void zero_deg_kernel() {
    int i = blockIdx.x * blockDim.x + threadIdx.x;
    int stride = gridDim.x * blockDim.x;
    for (int k = i; k < NQ_; k += stride) g_degQ[k] = 0;
    for (int k = i; k < NP_; k += stride) g_degP[k] = 0;
}

// ---------------------------------------------------------------------------
// CSR build step 2: count degrees (both edge directions in one launch)
// ---------------------------------------------------------------------------
__global__ __launch_bounds__(256) void degree_kernel(
    const int* __restrict__ dst_pv, const int* __restrict__ dst_vp, int nE)
{
    int i = blockIdx.x * blockDim.x + threadIdx.x;
    if (i < nE)              atomicAdd(&g_degQ[__ldg(dst_pv + i)], 1);
    else if (i < 2 * nE)     atomicAdd(&g_degP[__ldg(dst_vp + i - nE)], 1);
}

// ---------------------------------------------------------------------------
// CSR build step 3: exclusive scan of degrees -> offsets (+ cursor init).
// Two blocks of 1024 threads: block 0 -> Q side, block 1 -> P side.
// ---------------------------------------------------------------------------
__global__ __launch_bounds__(1024) void scan_kernel() {
    const bool qside = (blockIdx.x == 0);
    const int n   = qside ? NQ_ : NP_;
    int* deg = qside ? g_degQ : g_degP;
    int* off = qside ? g_offQ : g_offP;
    int* cur = qside ? g_curQ : g_curP;

    const int T = 1024;
    const int t = threadIdx.x;
    const int chunk = (n + T - 1) / T;
    const int lo = t * chunk;
    const int hi = (lo + chunk < n) ? lo + chunk : n;

    int s = 0;
    for (int i = lo; i < hi; ++i) s += deg[i];

    __shared__ int ps[T];
    ps[t] = s;
    __syncthreads();
    // Hillis-Steele inclusive scan
    for (int d = 1; d < T; d <<= 1) {
        int v = 0;
        if (t >= d) v = ps[t - d];
        __syncthreads();
        if (t >= d) ps[t] += v;
        __syncthreads();
    }
    int run = (t == 0) ? 0 : ps[t - 1];
    for (int i = lo; i < hi; ++i) {
        off[i] = run;
        cur[i] = run;
        run += deg[i];
    }
    if (t == 0) off[n] = ps[T - 1];
}

// ---------------------------------------------------------------------------
// CSR build step 4: fill edge lists
// ---------------------------------------------------------------------------
__global__ __launch_bounds__(256) void fill_kernel(
    const int* __restrict__ src_pv, const int* __restrict__ dst_pv,
    const int* __restrict__ src_vp, const int* __restrict__ dst_vp, int nE)
{
    int i = blockIdx.x * blockDim.x + threadIdx.x;
    if (i < nE) {
        int pos = atomicAdd(&g_curQ[__ldg(dst_pv + i)], 1);
        g_csrQ[pos] = __ldg(src_pv + i);
    } else if (i < 2 * nE) {
        int e = i - nE;
        int pos = atomicAdd(&g_curP[__ldg(dst_vp + e)], 1);
        g_csrP[pos] = __ldg(src_vp + e);
    }
}

// ---------------------------------------------------------------------------
// Gather-mean aggregation: one warp per destination node, no atomics.
// Warps [0,NQ) -> products (gather person rows); [NQ, NQ+NP) -> persons.
//   SRC_H: gather from layer-0 hidden state instead of the input x.
// ---------------------------------------------------------------------------
template <bool SRC_H>
__global__ __launch_bounds__(256) void agg_kernel(
    const float* __restrict__ x_p_in, const float* __restrict__ x_q_in)
{
    int gwarp = (int)((blockIdx.x * blockDim.x + threadIdx.x) >> 5);
    int lane = threadIdx.x & 31;
    if (gwarp >= NQ_ + NP_) return;

    const float* x;
    const int* off;
    const int* csr;
    float* out;
    int node;
    if (gwarp < NQ_) {
        node = gwarp;
        x = SRC_H ? g_hP : x_p_in;
        off = g_offQ; csr = g_csrQ; out = g_accQ;
    } else {
        node = gwarp - NQ_;
        x = SRC_H ? g_hQ : x_q_in;
        off = g_offP; csr = g_csrP; out = g_accP;
    }

    int beg = __ldg(off + node);
    int end = __ldg(off + node + 1);

    float4 s = make_float4(0.f, 0.f, 0.f, 0.f);
    int j = beg;
    for (; j + 4 <= end; j += 4) {
        int i0 = __ldg(csr + j);
        int i1 = __ldg(csr + j + 1);
        int i2 = __ldg(csr + j + 2);
        int i3 = __ldg(csr + j + 3);
        float4 v0 = *reinterpret_cast<const float4*>(x + (size_t)i0 * D_ + lane * 4);
        float4 v1 = *reinterpret_cast<const float4*>(x + (size_t)i1 * D_ + lane * 4);
        float4 v2 = *reinterpret_cast<const float4*>(x + (size_t)i2 * D_ + lane * 4);
        float4 v3 = *reinterpret_cast<const float4*>(x + (size_t)i3 * D_ + lane * 4);
        s.x += v0.x + v1.x + v2.x + v3.x;
        s.y += v0.y + v1.y + v2.y + v3.y;
        s.z += v0.z + v1.z + v2.z + v3.z;
        s.w += v0.w + v1.w + v2.w + v3.w;
    }
    for (; j < end; ++j) {
        int i0 = __ldg(csr + j);
        float4 v0 = *reinterpret_cast<const float4*>(x + (size_t)i0 * D_ + lane * 4);
        s.x += v0.x; s.y += v0.y; s.z += v0.z; s.w += v0.w;
    }

    int deg = end - beg;
    float r = 1.f / (float)(deg > 0 ? deg : 1);
    s.x *= r; s.y *= r; s.z *= r; s.w *= r;
    *reinterpret_cast<float4*>(out + (size_t)node * D_ + lane * 4) = s;
}

// ---------------------------------------------------------------------------
// Merged fused SAGE linear for one layer (both node types in one launch):
//   out = mean_acc @ Wl + self @ Wr + b   [+ReLU if !LAYER1]
// (mean already applied by agg_kernel; no per-row scaling here.)
// 128x128 tile, 256 threads, 8x8 microtile on packed f32x2 accumulators,
// double-buffered smem + register prefetch, conflict-free B reads.
// ---------------------------------------------------------------------------
#define BM 128
#define BK 16
#define AS_STRIDE 132
#define BS_STRIDE 132

template <bool LAYER1>
__global__ __launch_bounds__(256, 2) void gemm_kernel(
    const float* __restrict__ x_q_in, const float* __restrict__ x_p_in,
    const float* __restrict__ Wl_q, const float* __restrict__ Wr_q,
    const float* __restrict__ b_q,
    const float* __restrict__ Wl_p, const float* __restrict__ Wr_p,
    const float* __restrict__ b_p,
    float* __restrict__ out_q, float* __restrict__ out_p,
    int nQb)
{
    const bool qside = ((int)blockIdx.x) < nQb;
    const int blk = qside ? (int)blockIdx.x : (int)blockIdx.x - nQb;
    const int nrows = qside ? NQ_ : NP_;
    const float* accsrc = qside ? g_accQ : g_accP;
    const float* self   = LAYER1 ? (qside ? g_hQ : g_hP) : (qside ? x_q_in : x_p_in);
    const float* Wl     = qside ? Wl_q : Wl_p;
    const float* Wr     = qside ? Wr_q : Wr_p;
    const float* bias   = qside ? b_q  : b_p;
    float*       out    = LAYER1 ? (qside ? out_q : out_p) : (qside ? g_hQ : g_hP);

    __shared__ __align__(16) float As[2][BK][AS_STRIDE];  // [k][m]
    __shared__ __align__(16) float Bs[2][BK][BS_STRIDE];  // [k][n]

    const int tid = threadIdx.x;
    const int tx = tid & 15;     // column group
    const int ty = tid >> 4;     // row group: rows ty*8 .. ty*8+7
    const int row0 = blk * BM;

    // A-load mapping: thread owns 8 contiguous k of one row
    const int ar = tid >> 1;             // local row 0..127
    const int ah = (tid & 1) * 8;        // k sub-offset 0 or 8
    const int agrow = row0 + ar;
    // B-load mapping
    const int bkr = tid >> 4;            // k row 0..15
    const int bc  = (tid & 15) * 8;      // column 0..120

    unsigned long long accr[8][4];
#pragma unroll
    for (int i = 0; i < 8; i++)
#pragma unroll
        for (int j = 0; j < 4; j++) accr[i][j] = 0ull;

    float4 va0, va1, vb0, vb1;

    // ---- prefetch tile 0 (pass 0: A = acc, W = Wl, k0 = 0) ----
    va0 = make_float4(0.f, 0.f, 0.f, 0.f); va1 = va0;
    if (agrow < nrows) {
        const float* ap = accsrc + (size_t)agrow * D_ + ah;
        va0 = *reinterpret_cast<const float4*>(ap);
        va1 = *reinterpret_cast<const float4*>(ap + 4);
    }
    {
        const float* wp = Wl + (size_t)bkr * D_ + bc;
        vb0 = *reinterpret_cast<const float4*>(wp);
        vb1 = *reinterpret_cast<const float4*>(wp + 4);
    }
    // ---- store tile 0 ----
    {
        float v[8] = {va0.x, va0.y, va0.z, va0.w, va1.x, va1.y, va1.z, va1.w};
#pragma unroll
        for (int j = 0; j < 8; j++) As[0][ah + j][ar] = v[j];
        *reinterpret_cast<float4*>(&Bs[0][bkr][bc])     = vb0;
        *reinterpret_cast<float4*>(&Bs[0][bkr][bc + 4]) = vb1;
    }
    __syncthreads();

#pragma unroll 2
    for (int t = 0; t < 16; ++t) {
        const int buf = t & 1;

        // ---- prefetch next tile into registers ----
        if (t < 15) {
            int tn = t + 1;
            int k0 = (tn & 7) * BK;
            const float* A = (tn < 8) ? accsrc : self;
            const float* W = (tn < 8) ? Wl : Wr;
            va0 = make_float4(0.f, 0.f, 0.f, 0.f); va1 = va0;
            if (agrow < nrows) {
                const float* ap = A + (size_t)agrow * D_ + k0 + ah;
                va0 = *reinterpret_cast<const float4*>(ap);
                va1 = *reinterpret_cast<const float4*>(ap + 4);
            }
            const float* wp = W + (size_t)(k0 + bkr) * D_ + bc;
            vb0 = *reinterpret_cast<const float4*>(wp);
            vb1 = *reinterpret_cast<const float4*>(wp + 4);
        }

        // ---- compute current tile: 16 k-steps, 8x8 microtile ----
#pragma unroll
        for (int kk = 0; kk < BK; ++kk) {
            float4 a0 = *reinterpret_cast<const float4*>(&As[buf][kk][ty * 8]);
            float4 a1 = *reinterpret_cast<const float4*>(&As[buf][kk][ty * 8 + 4]);
            // conflict-free B reads: 16 threads x consecutive 16B
            ulonglong2 blo = *reinterpret_cast<const ulonglong2*>(&Bs[buf][kk][tx * 4]);
            ulonglong2 bhi = *reinterpret_cast<const ulonglong2*>(&Bs[buf][kk][64 + tx * 4]);
            unsigned long long bv[4] = {blo.x, blo.y, bhi.x, bhi.y};
            float av[8] = {a0.x, a0.y, a0.z, a0.w, a1.x, a1.y, a1.z, a1.w};
#pragma unroll
            for (int i = 0; i < 8; i++) {
                unsigned long long ap = pack2dup(av[i]);
                fma2(accr[i][0], ap, bv[0]);
                fma2(accr[i][1], ap, bv[1]);
                fma2(accr[i][2], ap, bv[2]);
                fma2(accr[i][3], ap, bv[3]);
            }
        }

        // ---- store prefetched tile into other buffer ----
        if (t < 15) {
            float v[8] = {va0.x, va0.y, va0.z, va0.w, va1.x, va1.y, va1.z, va1.w};
#pragma unroll
            for (int j = 0; j < 8; j++) As[buf ^ 1][ah + j][ar] = v[j];
            *reinterpret_cast<float4*>(&Bs[buf ^ 1][bkr][bc])     = vb0;
            *reinterpret_cast<float4*>(&Bs[buf ^ 1][bkr][bc + 4]) = vb1;
        }
        __syncthreads();
    }

    // ---- epilogue: bias, optional ReLU, store (cols tx*4 and 64+tx*4) ----
    float bcol[8];
#pragma unroll
    for (int j = 0; j < 4; j++) {
        bcol[j]     = bias[tx * 4 + j];
        bcol[4 + j] = bias[64 + tx * 4 + j];
    }

#pragma unroll
    for (int i = 0; i < 8; i++) {
        int r = row0 + ty * 8 + i;
        if (r >= nrows) continue;
        float o[8];
#pragma unroll
        for (int j = 0; j < 4; j++) {
            float2 v = unpack2(accr[i][j]);
            o[2 * j]     = v.x;
            o[2 * j + 1] = v.y;
        }
#pragma unroll
        for (int j = 0; j < 8; j++) {
            o[j] += bcol[j];
            if (!LAYER1) o[j] = fmaxf(o[j], 0.f);  // ReLU after layer 0 only
        }
        float* orow = out + (size_t)r * D_;
        *reinterpret_cast<float4*>(orow + tx * 4)      = make_float4(o[0], o[1], o[2], o[3]);
        *reinterpret_cast<float4*>(orow + 64 + tx * 4) = make_float4(o[4], o[5], o[6], o[7]);
    }
}

// ---------------------------------------------------------------------------
// kernel_launch — inputs classified by element count (see R4 notes)
// Output: [h_p (NP*D) | h_q (NQ*D)]
// ---------------------------------------------------------------------------
extern "C" void kernel_launch(void* const* d_in, const int* in_sizes, int n_in,
                              void* d_out, int out_size)
{
    (void)out_size;
    const float* x_p = nullptr;
    const float* x_q = nullptr;
    const float* W[8] = {nullptr};
    const float* b[4] = {nullptr};
    const int*   eidx[4] = {nullptr};
    int wi = 0, bi = 0, ei = 0;
    int E = E_;

    for (int i = 0; i < n_in; i++) {
        int n = in_sizes[i];
        if (n == NP_ * D_)            x_p = (const float*)d_in[i];
        else if (n == NQ_ * D_)       x_q = (const float*)d_in[i];
        else if (n == D_ * D_)        { if (wi < 8) W[wi++] = (const float*)d_in[i]; }
        else if (n == D_)             { if (bi < 4) b[bi++] = (const float*)d_in[i]; }
        else                          { if (ei < 4) { eidx[ei++] = (const int*)d_in[i]; E = n; } }
    }

    const int* src_pv = eidx[0];
    const int* dst_pv = eidx[1];
    const int* src_vp = eidx[2];
    const int* dst_vp = eidx[3];
    float* out = (float*)d_out;
    float* out_p = out;
    float* out_q = out + (size_t)NP_ * D_;

    int eblocks = (2 * E + 255) / 256;                     // one thread per edge
    int ablocks = ((NQ_ + NP_) * 32 + 255) / 256;          // one warp per node
    int nQb = (NQ_ + BM - 1) / BM;                         // 391
    int nPb = (NP_ + BM - 1) / BM;                         // 782
    dim3 gG(nQb + nPb);

    // ---- CSR build (once; topology shared by both layers) ----
    zero_deg_kernel<<<256, 256>>>();
    degree_kernel<<<eblocks, 256>>>(dst_pv, dst_vp, E);
    scan_kernel<<<2, 1024>>>();
    fill_kernel<<<eblocks, 256>>>(src_pv, dst_pv, src_vp, dst_vp, E);

    // ---- Layer 0 ----
    agg_kernel<false><<<ablocks, 256>>>(x_p, x_q);
    gemm_kernel<false><<<gG, 256>>>(x_q, x_p,
                                    W[0], W[1], b[0],     // product side (pv)
                                    W[2], W[3], b[1],     // person side (vp)
                                    nullptr, nullptr, nQb);

    // ---- Layer 1 ----
    agg_kernel<true><<<ablocks, 256>>>(x_p, x_q);
    gemm_kernel<true><<<gG, 256>>>(x_q, x_p,
                                   W[4], W[5], b[2],
                                   W[6], W[7], b[3],
                                   out_q, out_p, nQb);
}